// round 1
// baseline (speedup 1.0000x reference)
#include <cuda_runtime.h>

#define NTOK 32768
#define DDIM 256
#define KC   1024
#define HW   1024
#define TM   128
#define TK   128
#define DKC  32
#define DECAY_F 0.99f
#define ONE_M_DECAY 0.01f
#define EPS_F 1e-5f

// output offsets (concatenated float32 outputs in reference return order)
#define O_ZQ   0          // 32*256*32*32 = 8388608
#define O_IDX  8388608    // 32768
#define O_LOSS 8421376    // 1
#define O_EMB  8421377    // 262144
#define O_CS   8683521    // 1024
#define O_EAVG 8684545    // 262144
// total = 8946689

__device__ float g_es[KC * DDIM];
__device__ float g_cs[KC];
__device__ int   g_idx[NTOK];
__device__ float g_enorm[KC];
__device__ float g_partial[1024];
__device__ float g_n;

// ---------------------------------------------------------------------------
// ||e_k||^2 per code: warp per code
// ---------------------------------------------------------------------------
__global__ void enorm_kernel(const float* __restrict__ embed) {
    int w = threadIdx.x >> 5, lane = threadIdx.x & 31;
    int c = blockIdx.x * 8 + w;
    const float* row = embed + (size_t)c * DDIM;
    float s = 0.f;
#pragma unroll
    for (int i = 0; i < 8; i++) { float v = row[lane + i * 32]; s += v * v; }
#pragma unroll
    for (int off = 16; off; off >>= 1) s += __shfl_xor_sync(0xffffffffu, s, off);
    if (lane == 0) g_enorm[c] = s;
}

// ---------------------------------------------------------------------------
// Distance GEMM + argmin. Block: 128 tokens x all 1024 codes.
// Threads 256 = 16(tx: codes) x 16(ty: tokens). Per-thread 8x8 register tile.
// argmin needs only ||e||^2 - 2 x.e (||x||^2 is constant per row).
// ---------------------------------------------------------------------------
__global__ __launch_bounds__(256) void dist_kernel(
    const float* __restrict__ z, const float* __restrict__ embed,
    float* __restrict__ out)
{
    __shared__ float xs[DKC][TM];        // x tile, d-major rows of 128 tokens
    __shared__ float es[TK][DKC + 1];    // e tile, code-major, pad for banks

    int tid = threadIdx.x;
    int tx = tid & 15, ty = tid >> 4;
    int t0 = blockIdx.x * TM;            // 128 tokens, all inside one image
    int bimg = t0 >> 10;
    int hw0  = t0 & 1023;
    const float* zb = z + (size_t)bimg * DDIM * HW + hw0;

    float best[8];
    int   bestk[8];
#pragma unroll
    for (int i = 0; i < 8; i++) { best[i] = 3.4e38f; bestk[i] = 0; }

    for (int k0 = 0; k0 < KC; k0 += TK) {
        float acc[8][8];
#pragma unroll
        for (int i = 0; i < 8; i++)
#pragma unroll
            for (int j = 0; j < 8; j++) acc[i][j] = 0.f;

        for (int d0 = 0; d0 < DDIM; d0 += DKC) {
            __syncthreads();
            // load x tile: coalesced over tokens (hw contiguous)
#pragma unroll
            for (int l = 0; l < 16; l++) {
                int i2 = l * 256 + tid;
                int dd = i2 >> 7, t = i2 & 127;
                xs[dd][t] = zb[(size_t)(d0 + dd) * HW + t];
            }
            // load e tile: coalesced over d; conflict-free store (pad 33)
#pragma unroll
            for (int l = 0; l < 16; l++) {
                int i2 = l * 256 + tid;
                int dd = i2 & 31, kk = i2 >> 5;
                es[kk][dd] = embed[(size_t)(k0 + kk) * DDIM + d0 + dd];
            }
            __syncthreads();
#pragma unroll
            for (int dd = 0; dd < DKC; dd++) {
                float4 x0 = *(const float4*)&xs[dd][ty * 8];
                float4 x1 = *(const float4*)&xs[dd][ty * 8 + 4];
                float xv[8] = {x0.x, x0.y, x0.z, x0.w, x1.x, x1.y, x1.z, x1.w};
                float ev[8];
#pragma unroll
                for (int j = 0; j < 8; j++) ev[j] = es[j * 16 + tx][dd];
#pragma unroll
                for (int i = 0; i < 8; i++)
#pragma unroll
                    for (int j = 0; j < 8; j++)
                        acc[i][j] += xv[i] * ev[j];
            }
        }
        // fold this K-chunk into running per-token best (codes ascend in j)
#pragma unroll
        for (int j = 0; j < 8; j++) {
            int k = k0 + j * 16 + tx;
            float en = g_enorm[k];
#pragma unroll
            for (int i = 0; i < 8; i++) {
                float dst = en - 2.0f * acc[i][j];
                if (dst < best[i]) { best[i] = dst; bestk[i] = k; }
            }
        }
    }

    // reduce argmin across the 16 code-lanes (xor masks stay in 16-lane halves)
#pragma unroll
    for (int off = 8; off; off >>= 1) {
#pragma unroll
        for (int i = 0; i < 8; i++) {
            float ov = __shfl_xor_sync(0xffffffffu, best[i], off);
            int   ok = __shfl_xor_sync(0xffffffffu, bestk[i], off);
            if (ov < best[i] || (ov == best[i] && ok < bestk[i])) {
                best[i] = ov; bestk[i] = ok;
            }
        }
    }
    if (tx == 0) {
#pragma unroll
        for (int i = 0; i < 8; i++) {
            int t = t0 + ty * 8 + i;
            g_idx[t] = bestk[i];
            out[O_IDX + t] = (float)bestk[i];
            atomicAdd(&g_cs[bestk[i]], 1.0f);  // integer counts: exact
        }
    }
}

// ---------------------------------------------------------------------------
// Gather z_q (coalesced via smem transpose), vq_loss partials, es segment-sum
// Block: 32 tokens x 256 dims; 256 threads
// ---------------------------------------------------------------------------
__global__ __launch_bounds__(256) void gather_kernel(
    const float* __restrict__ z, const float* __restrict__ embed,
    float* __restrict__ out)
{
    __shared__ float s[32][DDIM + 1];
    __shared__ int   kidx[32];
    __shared__ float red[256];
    int tid = threadIdx.x;
    int t0 = blockIdx.x * 32;
    int bimg = t0 >> 10, hw0 = t0 & 1023;

    if (tid < 32) kidx[tid] = g_idx[t0 + tid];
    __syncthreads();
#pragma unroll
    for (int l = 0; l < 32; l++)
        s[l][tid] = embed[(size_t)kidx[l] * DDIM + tid];  // coalesced rows
    __syncthreads();

    int d0 = tid >> 5, ti = tid & 31;
    float lsum = 0.f;
    float* outz = out + O_ZQ;
#pragma unroll
    for (int m = 0; m < 32; m++) {
        int d = m * 8 + d0;
        float e = s[ti][d];                               // conflict-free (pad)
        size_t zoff = ((size_t)bimg * DDIM + d) * HW + hw0 + ti;
        float zv = z[zoff];
        outz[zoff] = e;                                   // z_q_st == z_q
        float df = zv - e;
        lsum += df * df;
        atomicAdd(&g_es[(size_t)kidx[ti] * DDIM + d], zv);
    }
    red[tid] = lsum;
    __syncthreads();
    for (int off = 128; off; off >>= 1) {
        if (tid < off) red[tid] += red[tid + off];
        __syncthreads();
    }
    if (tid == 0) g_partial[blockIdx.x] = red[0];
}

__global__ void loss_kernel(float* __restrict__ out) {
    __shared__ float red[256];
    int tid = threadIdx.x;
    float s = 0.f;
    for (int i = tid; i < 1024; i += 256) s += g_partial[i];
    red[tid] = s; __syncthreads();
    for (int off = 128; off; off >>= 1) {
        if (tid < off) red[tid] += red[tid + off];
        __syncthreads();
    }
    if (tid == 0) out[O_LOSS] = red[0] / 8388608.0f;
}

__global__ void ema_a_kernel(const float* __restrict__ cluster_size,
                             float* __restrict__ out) {
    __shared__ float red[1024];
    int k = threadIdx.x;
    float ncs = cluster_size[k] * DECAY_F + ONE_M_DECAY * g_cs[k];
    out[O_CS + k] = ncs;
    red[k] = ncs; __syncthreads();
    for (int off = 512; off; off >>= 1) {
        if (k < off) red[k] += red[k + off];
        __syncthreads();
    }
    if (k == 0) g_n = red[0];
}

__global__ void ema_b_kernel(const float* __restrict__ embed_avg,
                             float* __restrict__ out) {
    int idx = blockIdx.x * 256 + threadIdx.x;
    int k = idx >> 8;
    float nea = embed_avg[idx] * DECAY_F + ONE_M_DECAY * g_es[idx];
    out[O_EAVG + idx] = nea;
    float ncs = out[O_CS + k];
    float n = g_n;
    float csn = (ncs + EPS_F) / (n + KC * EPS_F) * n;
    out[O_EMB + idx] = nea / csn;
}

// ---------------------------------------------------------------------------
extern "C" void kernel_launch(void* const* d_in, const int* in_sizes, int n_in,
                              void* d_out, int out_size)
{
    const float* z            = (const float*)d_in[0];
    const float* embed        = (const float*)d_in[1];
    const float* cluster_size = (const float*)d_in[2];
    const float* embed_avg    = (const float*)d_in[3];
    float* out = (float*)d_out;

    void* p;
    cudaGetSymbolAddress(&p, g_es);
    cudaMemsetAsync(p, 0, KC * DDIM * sizeof(float));
    cudaGetSymbolAddress(&p, g_cs);
    cudaMemsetAsync(p, 0, KC * sizeof(float));

    enorm_kernel<<<128, 256>>>(embed);
    dist_kernel<<<NTOK / TM, 256>>>(z, embed, out);
    gather_kernel<<<NTOK / 32, 256>>>(z, embed, out);
    loss_kernel<<<1, 256>>>(out);
    ema_a_kernel<<<1, 1024>>>(cluster_size, out);
    ema_b_kernel<<<KC * DDIM / 256, 256>>>(embed_avg, out);
}

// round 2
// speedup vs baseline: 1.0239x; 1.0239x over previous
#include <cuda_runtime.h>

#define NTOK 32768
#define DDIM 256
#define KC   1024
#define HW   1024
#define TM   128
#define TK   128
#define DKC  32
#define DECAY_F 0.99f
#define ONE_M_DECAY 0.01f
#define EPS_F 1e-5f

// output offsets (concatenated float32 outputs in reference return order)
#define O_ZQ   0          // 32*256*32*32 = 8388608
#define O_IDX  8388608    // 32768
#define O_LOSS 8421376    // 1
#define O_EMB  8421377    // 262144
#define O_CS   8683521    // 1024
#define O_EAVG 8684545    // 262144

__device__ float g_es[KC * DDIM];
__device__ float g_cs[KC];
__device__ int   g_idx[NTOK];
__device__ float g_enorm[KC];
__device__ float g_partial[1024];
__device__ float g_n;

// packed fp32x2 FMA (FFMA2) — only reachable via explicit PTX on sm_103a
#define FMA2(d, a, b) \
    asm("fma.rn.f32x2 %0, %1, %2, %0;" : "+l"(d) : "l"(a), "l"(b))
#define UNPACK2(lo, hi, v) \
    asm("mov.b64 {%0, %1}, %2;" : "=f"(lo), "=f"(hi) : "l"(v))

// ---------------------------------------------------------------------------
// ||e_k||^2 per code: warp per code
// ---------------------------------------------------------------------------
__global__ void enorm_kernel(const float* __restrict__ embed) {
    int w = threadIdx.x >> 5, lane = threadIdx.x & 31;
    int c = blockIdx.x * 8 + w;
    const float* row = embed + (size_t)c * DDIM;
    float s = 0.f;
#pragma unroll
    for (int i = 0; i < 8; i++) { float v = row[lane + i * 32]; s += v * v; }
#pragma unroll
    for (int off = 16; off; off >>= 1) s += __shfl_xor_sync(0xffffffffu, s, off);
    if (lane == 0) g_enorm[c] = s;
}

// tiny pre-kernels: pad launch count so ncu (-s 5 -c 1) captures dist_kernel
__global__ void pre_a_kernel() { if (threadIdx.x == 0) g_n = 0.f; }
__global__ void pre_b_kernel() { g_partial[threadIdx.x] = 0.f; }

// ---------------------------------------------------------------------------
// Distance GEMM + argmin with packed f32x2 FMA.
// Block: 128 tokens x 128-code chunks (8 chunks). 256 thr = 16(tx:codes) x
// 16(ty:tokens). Per-thread: 8 tokens x 4 code-PAIRS, acc in 64-bit f32x2.
//  - xs2: x duplicated {v,v} so token operand is a natural 64-bit pair
//  - es:  code-major, stride 130 (bank-spread + 8B alignment of pairs)
// argmin needs only ||e||^2 - 2 x.e.
// ---------------------------------------------------------------------------
__global__ __launch_bounds__(256) void dist_kernel(
    const float* __restrict__ z, const float* __restrict__ embed,
    float* __restrict__ out)
{
    __shared__ float xs2[DKC][2 * TM];     // 32 KB, duplicated pairs
    __shared__ float es[DKC][TK + 2];      // 16.6 KB, stride 130

    int tid = threadIdx.x;
    int tx = tid & 15, ty = tid >> 4;
    int t0 = blockIdx.x * TM;
    int bimg = t0 >> 10;
    int hw0  = t0 & 1023;
    const float* zb = z + (size_t)bimg * DDIM * HW + hw0;

    float best[8];
    int   bestk[8];
#pragma unroll
    for (int i = 0; i < 8; i++) { best[i] = 3.4e38f; bestk[i] = 0; }

    for (int k0 = 0; k0 < KC; k0 += TK) {
        unsigned long long acc[8][4];
#pragma unroll
        for (int i = 0; i < 8; i++)
#pragma unroll
            for (int j = 0; j < 4; j++) acc[i][j] = 0ULL;

        for (int d0 = 0; d0 < DDIM; d0 += DKC) {
            __syncthreads();
            // x tile: coalesced gmem (tokens contiguous), duplicated store
#pragma unroll
            for (int l = 0; l < 16; l++) {
                int i2 = l * 256 + tid;
                int dd = i2 >> 7, t = i2 & 127;
                float v = zb[(size_t)(d0 + dd) * HW + t];
                *(float2*)&xs2[dd][2 * t] = make_float2(v, v);
            }
            // e tile: coalesced gmem over d; stride-130 store (2-way max)
#pragma unroll
            for (int l = 0; l < 16; l++) {
                int i2 = l * 256 + tid;
                int dd = i2 & 31, kk = i2 >> 5;
                es[dd][kk] = embed[(size_t)(k0 + kk) * DDIM + d0 + dd];
            }
            __syncthreads();
#pragma unroll 8
            for (int dd = 0; dd < DKC; dd++) {
                // 8 token pairs (v,v): 16 consecutive floats -> 4x LDS.128
                ulonglong2 xq[4];
#pragma unroll
                for (int q = 0; q < 4; q++)
                    xq[q] = *(const ulonglong2*)&xs2[dd][16 * ty + 4 * q];
                unsigned long long xx[8] = {xq[0].x, xq[0].y, xq[1].x, xq[1].y,
                                            xq[2].x, xq[2].y, xq[3].x, xq[3].y};
                // 4 adjacent-code pairs: conflict-free LDS.64
                unsigned long long ee[4];
#pragma unroll
                for (int jp = 0; jp < 4; jp++)
                    ee[jp] = *(const unsigned long long*)&es[dd][32 * jp + 2 * tx];
#pragma unroll
                for (int i = 0; i < 8; i++)
#pragma unroll
                    for (int jp = 0; jp < 4; jp++)
                        FMA2(acc[i][jp], xx[i], ee[jp]);
            }
        }
        // fold chunk into running argmin (codes ascend: jp, then lo->hi)
#pragma unroll
        for (int jp = 0; jp < 4; jp++) {
            int c0 = k0 + 32 * jp + 2 * tx;
            float2 en = *(const float2*)&g_enorm[c0];
#pragma unroll
            for (int i = 0; i < 8; i++) {
                float lo, hi;
                UNPACK2(lo, hi, acc[i][jp]);
                float dlo = en.x - 2.0f * lo;
                float dhi = en.y - 2.0f * hi;
                if (dlo < best[i]) { best[i] = dlo; bestk[i] = c0; }
                if (dhi < best[i]) { best[i] = dhi; bestk[i] = c0 + 1; }
            }
        }
    }

    // reduce argmin across the 16 code-lanes (xor stays in 16-lane halves)
#pragma unroll
    for (int off = 8; off; off >>= 1) {
#pragma unroll
        for (int i = 0; i < 8; i++) {
            float ov = __shfl_xor_sync(0xffffffffu, best[i], off);
            int   ok = __shfl_xor_sync(0xffffffffu, bestk[i], off);
            if (ov < best[i] || (ov == best[i] && ok < bestk[i])) {
                best[i] = ov; bestk[i] = ok;
            }
        }
    }
    if (tx == 0) {
#pragma unroll
        for (int i = 0; i < 8; i++) {
            int t = t0 + ty * 8 + i;
            g_idx[t] = bestk[i];
            out[O_IDX + t] = (float)bestk[i];
            atomicAdd(&g_cs[bestk[i]], 1.0f);  // integer counts: exact
        }
    }
}

// ---------------------------------------------------------------------------
// Gather z_q (coalesced via smem transpose), vq_loss partials, es segment-sum
// ---------------------------------------------------------------------------
__global__ __launch_bounds__(256) void gather_kernel(
    const float* __restrict__ z, const float* __restrict__ embed,
    float* __restrict__ out)
{
    __shared__ float s[32][DDIM + 1];
    __shared__ int   kidx[32];
    __shared__ float red[256];
    int tid = threadIdx.x;
    int t0 = blockIdx.x * 32;
    int bimg = t0 >> 10, hw0 = t0 & 1023;

    if (tid < 32) kidx[tid] = g_idx[t0 + tid];
    __syncthreads();
#pragma unroll
    for (int l = 0; l < 32; l++)
        s[l][tid] = embed[(size_t)kidx[l] * DDIM + tid];  // coalesced rows
    __syncthreads();

    int d0 = tid >> 5, ti = tid & 31;
    float lsum = 0.f;
    float* outz = out + O_ZQ;
#pragma unroll
    for (int m = 0; m < 32; m++) {
        int d = m * 8 + d0;
        float e = s[ti][d];
        size_t zoff = ((size_t)bimg * DDIM + d) * HW + hw0 + ti;
        float zv = z[zoff];
        outz[zoff] = e;                                   // z_q_st == z_q
        float df = zv - e;
        lsum += df * df;
        atomicAdd(&g_es[(size_t)kidx[ti] * DDIM + d], zv);
    }
    red[tid] = lsum;
    __syncthreads();
    for (int off = 128; off; off >>= 1) {
        if (tid < off) red[tid] += red[tid + off];
        __syncthreads();
    }
    if (tid == 0) g_partial[blockIdx.x] = red[0];
}

__global__ void loss_kernel(float* __restrict__ out) {
    __shared__ float red[256];
    int tid = threadIdx.x;
    float s = 0.f;
    for (int i = tid; i < 1024; i += 256) s += g_partial[i];
    red[tid] = s; __syncthreads();
    for (int off = 128; off; off >>= 1) {
        if (tid < off) red[tid] += red[tid + off];
        __syncthreads();
    }
    if (tid == 0) out[O_LOSS] = red[0] / 8388608.0f;
}

__global__ void ema_a_kernel(const float* __restrict__ cluster_size,
                             float* __restrict__ out) {
    __shared__ float red[1024];
    int k = threadIdx.x;
    float ncs = cluster_size[k] * DECAY_F + ONE_M_DECAY * g_cs[k];
    out[O_CS + k] = ncs;
    red[k] = ncs; __syncthreads();
    for (int off = 512; off; off >>= 1) {
        if (k < off) red[k] += red[k + off];
        __syncthreads();
    }
    if (k == 0) g_n = red[0];
}

__global__ void ema_b_kernel(const float* __restrict__ embed_avg,
                             float* __restrict__ out) {
    int idx = blockIdx.x * 256 + threadIdx.x;
    int k = idx >> 8;
    float nea = embed_avg[idx] * DECAY_F + ONE_M_DECAY * g_es[idx];
    out[O_EAVG + idx] = nea;
    float ncs = out[O_CS + k];
    float n = g_n;
    float csn = (ncs + EPS_F) / (n + KC * EPS_F) * n;
    out[O_EMB + idx] = nea / csn;
}

// ---------------------------------------------------------------------------
extern "C" void kernel_launch(void* const* d_in, const int* in_sizes, int n_in,
                              void* d_out, int out_size)
{
    const float* z            = (const float*)d_in[0];
    const float* embed        = (const float*)d_in[1];
    const float* cluster_size = (const float*)d_in[2];
    const float* embed_avg    = (const float*)d_in[3];
    float* out = (float*)d_out;

    void* p;
    cudaGetSymbolAddress(&p, g_es);
    cudaMemsetAsync(p, 0, KC * DDIM * sizeof(float));   // launch 1
    cudaGetSymbolAddress(&p, g_cs);
    cudaMemsetAsync(p, 0, KC * sizeof(float));          // launch 2

    enorm_kernel<<<128, 256>>>(embed);                  // launch 3
    pre_a_kernel<<<1, 32>>>();                          // launch 4
    pre_b_kernel<<<1, 1024>>>();                        // launch 5
    dist_kernel<<<NTOK / TM, 256>>>(z, embed, out);     // launch 6 <- ncu -s 5
    gather_kernel<<<NTOK / 32, 256>>>(z, embed, out);
    loss_kernel<<<1, 256>>>(out);
    ema_a_kernel<<<1, 1024>>>(cluster_size, out);
    ema_b_kernel<<<KC * DDIM / 256, 256>>>(embed_avg, out);
}

// round 4
// speedup vs baseline: 1.3556x; 1.3240x over previous
#include <cuda_runtime.h>
#include <cuda_bf16.h>
#include <cstdint>

#define NTOK 32768
#define DDIM 256
#define KC   1024
#define HW   1024
#define DECAY_F 0.99f
#define ONE_M_DECAY 0.01f
#define EPS_F 1e-5f

// output offsets (concatenated float32 outputs in reference return order)
#define O_ZQ   0
#define O_IDX  8388608
#define O_LOSS 8421376
#define O_EMB  8421377
#define O_CS   8683521
#define O_EAVG 8684545

__device__ float g_es[KC * DDIM];
__device__ float g_cs[KC];
__device__ int   g_idx[NTOK];
__device__ float g_enorm[KC];
__device__ float g_partial[1024];
__device__ float g_n;

// bf16 3-way splits of x (tokens x D) and e (codes x D), row-major K-contig
__device__ __align__(16) __nv_bfloat16 g_ax0[NTOK * DDIM];
__device__ __align__(16) __nv_bfloat16 g_ax1[NTOK * DDIM];
__device__ __align__(16) __nv_bfloat16 g_ax2[NTOK * DDIM];
__device__ __align__(16) __nv_bfloat16 g_be0[KC * DDIM];
__device__ __align__(16) __nv_bfloat16 g_be1[KC * DDIM];
__device__ __align__(16) __nv_bfloat16 g_be2[KC * DDIM];

__device__ __forceinline__ uint32_t smem_u32(const void* p) {
    uint32_t a;
    asm("{ .reg .u64 t; cvta.to.shared.u64 t, %1; cvt.u32.u64 %0, t; }"
        : "=r"(a) : "l"(p));
    return a;
}

// mma.m16n8k16 row.col bf16 -> fp32 accumulate (sm_80 baseline PTX: compiles
// at compute_103, runs on the tensor pipe)
__device__ __forceinline__ void mma16816(float* c, const uint32_t* a,
                                         uint32_t b0, uint32_t b1) {
    asm volatile(
        "mma.sync.aligned.m16n8k16.row.col.f32.bf16.bf16.f32 "
        "{%0,%1,%2,%3}, {%4,%5,%6,%7}, {%8,%9}, {%0,%1,%2,%3};"
        : "+f"(c[0]), "+f"(c[1]), "+f"(c[2]), "+f"(c[3])
        : "r"(a[0]), "r"(a[1]), "r"(a[2]), "r"(a[3]), "r"(b0), "r"(b1));
}

#define LDSM_X4(r0, r1, r2, r3, addr) \
    asm volatile("ldmatrix.sync.aligned.m8n8.x4.shared.b16 {%0,%1,%2,%3}, [%4];" \
        : "=r"(r0), "=r"(r1), "=r"(r2), "=r"(r3) : "r"(addr))

// ---------------------------------------------------------------------------
// ||e_k||^2 per code (exact fp32)
// ---------------------------------------------------------------------------
__global__ void enorm_kernel(const float* __restrict__ embed) {
    int w = threadIdx.x >> 5, lane = threadIdx.x & 31;
    int c = blockIdx.x * 8 + w;
    const float* row = embed + (size_t)c * DDIM;
    float s = 0.f;
#pragma unroll
    for (int i = 0; i < 8; i++) { float v = row[lane + i * 32]; s += v * v; }
#pragma unroll
    for (int off = 16; off; off >>= 1) s += __shfl_xor_sync(0xffffffffu, s, off);
    if (lane == 0) g_enorm[c] = s;
}

// ---------------------------------------------------------------------------
// bf16 3-way split prep: v = hi + mid + lo (+ ~2^-25 residual)
// ---------------------------------------------------------------------------
__device__ __forceinline__ void split3(float v, __nv_bfloat16& h,
                                       __nv_bfloat16& m, __nv_bfloat16& l) {
    h = __float2bfloat16_rn(v);
    float r = v - __bfloat162float(h);
    m = __float2bfloat16_rn(r);
    float r2 = r - __bfloat162float(m);
    l = __float2bfloat16_rn(r2);
}

__global__ __launch_bounds__(256) void split_e_kernel(const float* __restrict__ embed) {
    int i = blockIdx.x * 256 + threadIdx.x;
    __nv_bfloat16 h, m, l;
    split3(embed[i], h, m, l);
    g_be0[i] = h; g_be1[i] = m; g_be2[i] = l;
}

// token-transpose + split: flat[t][d] = z[b][d][hw]
__global__ __launch_bounds__(256) void split_x_kernel(const float* __restrict__ z) {
    __shared__ float s[32][DDIM + 1];
    int tid = threadIdx.x;
    int t0 = blockIdx.x * 32;
    int bimg = t0 >> 10, hw0 = t0 & 1023;
    int d0 = tid >> 5, ti = tid & 31;
#pragma unroll
    for (int mrow = 0; mrow < 32; mrow++) {
        int d = mrow * 8 + d0;
        s[ti][d] = z[((size_t)bimg * DDIM + d) * HW + hw0 + ti];
    }
    __syncthreads();
#pragma unroll
    for (int l = 0; l < 32; l++) {
        size_t o = (size_t)(t0 + l) * DDIM + tid;
        __nv_bfloat16 h, m, lo;
        split3(s[l][tid], h, m, lo);
        g_ax0[o] = h; g_ax1[o] = m; g_ax2[o] = lo;
    }
}

// ---------------------------------------------------------------------------
// Distance + argmin via warp-MMA bf16x6 emulated-fp32 GEMM.
// Grid 128 CTAs x 256 thr (one wave). CTA: 256 tokens x all 1024 codes.
// n-chunks of 128 codes: stage 3 e-splits x full D=256 in smem (192KB,
// XOR-swizzled 512B rows, conflict-free ldmatrix.x4), then 2 token
// sub-blocks of 128 (warp tile m16 x n128) x 16 ksteps of k16.
// A frags come straight from gmem (LDG.32 matches mma A layout).
// smem: [0..4KB) enorm, [4KB..) B splits (64KB each).
// ---------------------------------------------------------------------------
#define SMEM_TOTAL (4096 + 3 * 65536)

__global__ __launch_bounds__(256, 1) void dist_hmma_kernel(float* __restrict__ out)
{
    extern __shared__ __align__(1024) char smem[];
    float* s_enorm = (float*)smem;
    uint32_t sb = smem_u32(smem);
    int tid = threadIdx.x, wid = tid >> 5, lane = tid & 31;
    int t0 = blockIdx.x * 256;

    int group = lane >> 2;            // fragment row within 8-group
    int tq = (lane & 3) * 2;          // fragment col pair base
    int bn = (lane & 7) + ((lane >> 4) << 3);  // ldmatrix n-row within n16
    int bkh = (lane >> 3) & 1;                 // ldmatrix k-half

#pragma unroll
    for (int i = 0; i < 4; i++) s_enorm[i * 256 + tid] = g_enorm[i * 256 + tid];

    float best[4];
    int   bestk[4];
#pragma unroll
    for (int i = 0; i < 4; i++) { best[i] = 3.4e38f; bestk[i] = 0; }

    const char* abase0 = (const char*)g_ax0;
    const char* abase1 = (const char*)g_ax1;
    const char* abase2 = (const char*)g_ax2;
    const char* bbase0 = (const char*)g_be0;
    const char* bbase1 = (const char*)g_be1;
    const char* bbase2 = (const char*)g_be2;

#pragma unroll 1
    for (int nc = 0; nc < 8; nc++) {
        int n0 = nc * 128;
        __syncthreads();
        // ---- stage B: 3 splits x 128 codes x 512B, swizzled ----
#pragma unroll
        for (int it = 0; it < 48; it++) {
            int id = it * 256 + tid;
            int s = id >> 12, rem = id & 4095, n = rem >> 5, col = rem & 31;
            const char* gb = (s == 0) ? bbase0 : (s == 1) ? bbase1 : bbase2;
            uint4 v = *(const uint4*)(gb + (size_t)(n0 + n) * 512 + col * 16);
            *(uint4*)(smem + 4096 + (s << 16) + n * 512 + ((col ^ (n & 7)) << 4)) = v;
        }
        __syncthreads();

#pragma unroll 1
        for (int tb = 0; tb < 2; tb++) {
            float acc[16][4];
#pragma unroll
            for (int i = 0; i < 16; i++)
#pragma unroll
                for (int j = 0; j < 4; j++) acc[i][j] = 0.f;

            int mrow = t0 + tb * 128 + wid * 16;
            size_t arow = ((size_t)(mrow + group) * 256 + tq) * 2;

#pragma unroll 2
            for (int ks = 0; ks < 16; ks++) {
                int k0 = ks * 16;
                uint32_t a[3][4];
                size_t o = arow + k0 * 2;
                a[0][0] = *(const uint32_t*)(abase0 + o);
                a[0][1] = *(const uint32_t*)(abase0 + o + 4096);
                a[0][2] = *(const uint32_t*)(abase0 + o + 16);
                a[0][3] = *(const uint32_t*)(abase0 + o + 4112);
                a[1][0] = *(const uint32_t*)(abase1 + o);
                a[1][1] = *(const uint32_t*)(abase1 + o + 4096);
                a[1][2] = *(const uint32_t*)(abase1 + o + 16);
                a[1][3] = *(const uint32_t*)(abase1 + o + 4112);
                a[2][0] = *(const uint32_t*)(abase2 + o);
                a[2][1] = *(const uint32_t*)(abase2 + o + 4096);
                a[2][2] = *(const uint32_t*)(abase2 + o + 16);
                a[2][3] = *(const uint32_t*)(abase2 + o + 4112);

#pragma unroll
                for (int nt = 0; nt < 8; nt++) {
                    int nl = nt * 16 + bn;
                    uint32_t baddr = sb + 4096 + nl * 512 +
                                     (((ks * 2 + bkh) ^ (nl & 7)) << 4);
                    uint32_t b[3][4];
                    LDSM_X4(b[0][0], b[0][1], b[0][2], b[0][3], baddr);
                    LDSM_X4(b[1][0], b[1][1], b[1][2], b[1][3], baddr + 65536);
                    LDSM_X4(b[2][0], b[2][1], b[2][2], b[2][3], baddr + 131072);
                    float* c0 = acc[nt * 2];
                    float* c1 = acc[nt * 2 + 1];
                    // 6 split-terms: hh, hm, mh, mm, lh, hl
                    mma16816(c0, a[0], b[0][0], b[0][1]);
                    mma16816(c1, a[0], b[0][2], b[0][3]);
                    mma16816(c0, a[0], b[1][0], b[1][1]);
                    mma16816(c1, a[0], b[1][2], b[1][3]);
                    mma16816(c0, a[1], b[0][0], b[0][1]);
                    mma16816(c1, a[1], b[0][2], b[0][3]);
                    mma16816(c0, a[1], b[1][0], b[1][1]);
                    mma16816(c1, a[1], b[1][2], b[1][3]);
                    mma16816(c0, a[2], b[0][0], b[0][1]);
                    mma16816(c1, a[2], b[0][2], b[0][3]);
                    mma16816(c0, a[0], b[2][0], b[2][1]);
                    mma16816(c1, a[0], b[2][2], b[2][3]);
                }
            }
            // ---- fold argmin: dist = ||e||^2 - 2 acc ----
#pragma unroll
            for (int nt = 0; nt < 8; nt++)
#pragma unroll
                for (int t = 0; t < 2; t++) {
                    float* c = acc[nt * 2 + t];
                    int cb = n0 + nt * 16 + t * 8 + tq;
                    float e0 = s_enorm[cb], e1 = s_enorm[cb + 1];
                    float d0 = e0 - 2.f * c[0];
                    float d1 = e1 - 2.f * c[1];
                    float d2 = e0 - 2.f * c[2];
                    float d3 = e1 - 2.f * c[3];
                    int bi = tb * 2;
                    if (d0 < best[bi]) { best[bi] = d0; bestk[bi] = cb; }
                    if (d1 < best[bi]) { best[bi] = d1; bestk[bi] = cb + 1; }
                    if (d2 < best[bi + 1]) { best[bi + 1] = d2; bestk[bi + 1] = cb; }
                    if (d3 < best[bi + 1]) { best[bi + 1] = d3; bestk[bi + 1] = cb + 1; }
                }
        }
    }

    // reduce across the 4 lanes of each quad (they share token rows)
#pragma unroll
    for (int off = 1; off <= 2; off <<= 1)
#pragma unroll
        for (int i = 0; i < 4; i++) {
            float ov = __shfl_xor_sync(0xffffffffu, best[i], off);
            int   ok = __shfl_xor_sync(0xffffffffu, bestk[i], off);
            if (ov < best[i] || (ov == best[i] && ok < bestk[i])) {
                best[i] = ov; bestk[i] = ok;
            }
        }
    if ((lane & 3) == 0) {
#pragma unroll
        for (int tb = 0; tb < 2; tb++)
#pragma unroll
            for (int h = 0; h < 2; h++) {
                int t = t0 + tb * 128 + wid * 16 + group + h * 8;
                int bk = bestk[tb * 2 + h];
                g_idx[t] = bk;
                out[O_IDX + t] = (float)bk;
                atomicAdd(&g_cs[bk], 1.0f);
            }
    }
}

// ---------------------------------------------------------------------------
// Gather z_q, vq_loss partials, es segment-sum
// ---------------------------------------------------------------------------
__global__ __launch_bounds__(256) void gather_kernel(
    const float* __restrict__ z, const float* __restrict__ embed,
    float* __restrict__ out)
{
    __shared__ float s[32][DDIM + 1];
    __shared__ int   kidx[32];
    __shared__ float red[256];
    int tid = threadIdx.x;
    int t0 = blockIdx.x * 32;
    int bimg = t0 >> 10, hw0 = t0 & 1023;

    if (tid < 32) kidx[tid] = g_idx[t0 + tid];
    __syncthreads();
#pragma unroll
    for (int l = 0; l < 32; l++)
        s[l][tid] = embed[(size_t)kidx[l] * DDIM + tid];
    __syncthreads();

    int d0 = tid >> 5, ti = tid & 31;
    float lsum = 0.f;
    float* outz = out + O_ZQ;
#pragma unroll
    for (int m = 0; m < 32; m++) {
        int d = m * 8 + d0;
        float e = s[ti][d];
        size_t zoff = ((size_t)bimg * DDIM + d) * HW + hw0 + ti;
        float zv = z[zoff];
        outz[zoff] = e;
        float df = zv - e;
        lsum += df * df;
        atomicAdd(&g_es[(size_t)kidx[ti] * DDIM + d], zv);
    }
    red[tid] = lsum;
    __syncthreads();
    for (int off = 128; off; off >>= 1) {
        if (tid < off) red[tid] += red[tid + off];
        __syncthreads();
    }
    if (tid == 0) g_partial[blockIdx.x] = red[0];
}

__global__ void loss_kernel(float* __restrict__ out) {
    __shared__ float red[256];
    int tid = threadIdx.x;
    float s = 0.f;
    for (int i = tid; i < 1024; i += 256) s += g_partial[i];
    red[tid] = s; __syncthreads();
    for (int off = 128; off; off >>= 1) {
        if (tid < off) red[tid] += red[tid + off];
        __syncthreads();
    }
    if (tid == 0) out[O_LOSS] = red[0] / 8388608.0f;
}

__global__ void ema_a_kernel(const float* __restrict__ cluster_size,
                             float* __restrict__ out) {
    __shared__ float red[1024];
    int k = threadIdx.x;
    float ncs = cluster_size[k] * DECAY_F + ONE_M_DECAY * g_cs[k];
    out[O_CS + k] = ncs;
    red[k] = ncs; __syncthreads();
    for (int off = 512; off; off >>= 1) {
        if (k < off) red[k] += red[k + off];
        __syncthreads();
    }
    if (k == 0) g_n = red[0];
}

__global__ void ema_b_kernel(const float* __restrict__ embed_avg,
                             float* __restrict__ out) {
    int idx = blockIdx.x * 256 + threadIdx.x;
    int k = idx >> 8;
    float nea = embed_avg[idx] * DECAY_F + ONE_M_DECAY * g_es[idx];
    out[O_EAVG + idx] = nea;
    float ncs = out[O_CS + k];
    float n = g_n;
    float csn = (ncs + EPS_F) / (n + KC * EPS_F) * n;
    out[O_EMB + idx] = nea / csn;
}

// ---------------------------------------------------------------------------
extern "C" void kernel_launch(void* const* d_in, const int* in_sizes, int n_in,
                              void* d_out, int out_size)
{
    const float* z            = (const float*)d_in[0];
    const float* embed        = (const float*)d_in[1];
    const float* cluster_size = (const float*)d_in[2];
    const float* embed_avg    = (const float*)d_in[3];
    float* out = (float*)d_out;

    cudaFuncSetAttribute(dist_hmma_kernel,
                         cudaFuncAttributeMaxDynamicSharedMemorySize, SMEM_TOTAL);

    void* p;
    cudaGetSymbolAddress(&p, g_es);
    cudaMemsetAsync(p, 0, KC * DDIM * sizeof(float));        // launch 1
    cudaGetSymbolAddress(&p, g_cs);
    cudaMemsetAsync(p, 0, KC * sizeof(float));               // launch 2

    enorm_kernel<<<128, 256>>>(embed);                       // launch 3
    split_e_kernel<<<KC * DDIM / 256, 256>>>(embed);         // launch 4
    split_x_kernel<<<NTOK / 32, 256>>>(z);                   // launch 5
    dist_hmma_kernel<<<NTOK / 256, 256, SMEM_TOTAL>>>(out);  // launch 6 <- ncu
    gather_kernel<<<NTOK / 32, 256>>>(z, embed, out);
    loss_kernel<<<1, 256>>>(out);
    ema_a_kernel<<<1, 1024>>>(cluster_size, out);
    ema_b_kernel<<<KC * DDIM / 256, 256>>>(embed_avg, out);
}

// round 5
// speedup vs baseline: 2.0583x; 1.5184x over previous
#include <cuda_runtime.h>
#include <cuda_bf16.h>
#include <cstdint>

#define NTOK 32768
#define DDIM 256
#define KC   1024
#define HW   1024
#define DECAY_F 0.99f
#define ONE_M_DECAY 0.01f
#define EPS_F 1e-5f

// output offsets (concatenated float32 outputs in reference return order)
#define O_ZQ   0
#define O_IDX  8388608
#define O_LOSS 8421376
#define O_EMB  8421377
#define O_CS   8683521
#define O_EAVG 8684545

__device__ float g_es[KC * DDIM];
__device__ float g_cs[KC];
__device__ int   g_idx[NTOK];
__device__ float g_enorm[KC];
__device__ float g_partial[1024];
__device__ float g_n;

// A splits in mma-FRAGMENT-MAJOR layout: u32 idx = tblk16*2048 + ks*128 + lane*4 + frag
__device__ __align__(16) uint32_t g_ax0f[NTOK * 128];
__device__ __align__(16) uint32_t g_ax1f[NTOK * 128];
__device__ __align__(16) uint32_t g_ax2f[NTOK * 128];
// B splits row-major (code-major, 512B rows)
__device__ __align__(16) __nv_bfloat16 g_be0[KC * DDIM];
__device__ __align__(16) __nv_bfloat16 g_be1[KC * DDIM];
__device__ __align__(16) __nv_bfloat16 g_be2[KC * DDIM];

__device__ __forceinline__ uint32_t smem_u32(const void* p) {
    uint32_t a;
    asm("{ .reg .u64 t; cvta.to.shared.u64 t, %1; cvt.u32.u64 %0, t; }"
        : "=r"(a) : "l"(p));
    return a;
}

__device__ __forceinline__ void mma16816(float* c, const uint32_t* a,
                                         uint32_t b0, uint32_t b1) {
    asm volatile(
        "mma.sync.aligned.m16n8k16.row.col.f32.bf16.bf16.f32 "
        "{%0,%1,%2,%3}, {%4,%5,%6,%7}, {%8,%9}, {%0,%1,%2,%3};"
        : "+f"(c[0]), "+f"(c[1]), "+f"(c[2]), "+f"(c[3])
        : "r"(a[0]), "r"(a[1]), "r"(a[2]), "r"(a[3]), "r"(b0), "r"(b1));
}

#define LDSM_X4(r0, r1, r2, r3, addr) \
    asm volatile("ldmatrix.sync.aligned.m8n8.x4.shared.b16 {%0,%1,%2,%3}, [%4];" \
        : "=r"(r0), "=r"(r1), "=r"(r2), "=r"(r3) : "r"(addr))

#define CP_ASYNC16(dst, src) \
    asm volatile("cp.async.cg.shared.global [%0], [%1], 16;" \
                 :: "r"(dst), "l"(src) : "memory")
#define CP_COMMIT() asm volatile("cp.async.commit_group;" ::: "memory")

// ---------------------------------------------------------------------------
__global__ void enorm_kernel(const float* __restrict__ embed) {
    int w = threadIdx.x >> 5, lane = threadIdx.x & 31;
    int c = blockIdx.x * 8 + w;
    const float* row = embed + (size_t)c * DDIM;
    float s = 0.f;
#pragma unroll
    for (int i = 0; i < 8; i++) { float v = row[lane + i * 32]; s += v * v; }
#pragma unroll
    for (int off = 16; off; off >>= 1) s += __shfl_xor_sync(0xffffffffu, s, off);
    if (lane == 0) g_enorm[c] = s;
}

__device__ __forceinline__ void split3(float v, __nv_bfloat16& h,
                                       __nv_bfloat16& m, __nv_bfloat16& l) {
    h = __float2bfloat16_rn(v);
    float r = v - __bfloat162float(h);
    m = __float2bfloat16_rn(r);
    float r2 = r - __bfloat162float(m);
    l = __float2bfloat16_rn(r2);
}

__global__ __launch_bounds__(256) void split_e_kernel(const float* __restrict__ embed) {
    int i = blockIdx.x * 256 + threadIdx.x;
    __nv_bfloat16 h, m, l;
    split3(embed[i], h, m, l);
    g_be0[i] = h; g_be1[i] = m; g_be2[i] = l;
}

// token-transpose + split + fragment-major pack
__global__ __launch_bounds__(256) void split_x_kernel(const float* __restrict__ z) {
    __shared__ float s[32][257];
    int tid = threadIdx.x;
    int t0 = blockIdx.x * 32;
    int bimg = t0 >> 10, hw0 = t0 & 1023;
    int d0 = tid >> 5, ti = tid & 31;
#pragma unroll
    for (int mrow = 0; mrow < 32; mrow++) {
        int d = mrow * 8 + d0;
        s[ti][d] = z[((size_t)bimg * DDIM + d) * HW + hw0 + ti];
    }
    __syncthreads();
    size_t obase = (size_t)(t0 >> 4) * 2048;
#pragma unroll
    for (int i = 0; i < 16; i++) {
        int j = i * 256 + tid;
        int tbl = j >> 11, r = j & 2047;
        int ks = r >> 7, L = (r >> 2) & 31, f = r & 3;
        int g = L >> 2, q = L & 3, half = f & 1, kh = f >> 1;
        int tl = tbl * 16 + half * 8 + g;
        int d = ks * 16 + kh * 8 + q * 2;
        float v0 = s[tl][d], v1 = s[tl][d + 1];
        __nv_bfloat16 h0, m0, l0, h1, m1, l1;
        split3(v0, h0, m0, l0);
        split3(v1, h1, m1, l1);
        g_ax0f[obase + j] = ((uint32_t)__bfloat16_as_ushort(h1) << 16) | __bfloat16_as_ushort(h0);
        g_ax1f[obase + j] = ((uint32_t)__bfloat16_as_ushort(m1) << 16) | __bfloat16_as_ushort(m0);
        g_ax2f[obase + j] = ((uint32_t)__bfloat16_as_ushort(l1) << 16) | __bfloat16_as_ushort(l0);
    }
}

// ---------------------------------------------------------------------------
// Distance + argmin: warp-MMA bf16x6 emulated fp32. Grid 128 x 256 thr.
// CTA = 256 tokens (8 warps x m32) x 1024 codes in 16 n-chunks of 64.
// B double-buffered in smem via cp.async; A via contiguous LDG.128
// (fragment-major layout). smem: 4KB enorm + 2 x 96KB B buffers.
// ---------------------------------------------------------------------------
#define BUF_BYTES 98304
#define SMEM_TOTAL (4096 + 2 * BUF_BYTES)

__global__ __launch_bounds__(256, 1) void dist_hmma_kernel(float* __restrict__ out)
{
    extern __shared__ __align__(1024) char smem[];
    float* s_enorm = (float*)smem;
    uint32_t sb = smem_u32(smem);
    int tid = threadIdx.x, wid = tid >> 5, lane = tid & 31;
    int t0 = blockIdx.x * 256;
    int group = lane >> 2, tq = lane & 3;
    int bn = (lane & 7) + ((lane >> 4) << 3);
    int bkh = (lane >> 3) & 1;

#pragma unroll
    for (int i = 0; i < 4; i++) s_enorm[i * 256 + tid] = g_enorm[i * 256 + tid];

    // per-warp A offsets (u32 elements), fragment-major
    size_t abase[2];
#pragma unroll
    for (int mt = 0; mt < 2; mt++)
        abase[mt] = (size_t)(blockIdx.x * 16 + wid * 2 + mt) * 2048 + lane * 4;

    float best[4];
    int   bestk[4];
#pragma unroll
    for (int i = 0; i < 4; i++) { best[i] = 3.4e38f; bestk[i] = 0; }

    const char* bsrc[3] = {(const char*)g_be0, (const char*)g_be1, (const char*)g_be2};

    // ---- stage chunk 0 ----
#pragma unroll
    for (int it = 0; it < 24; it++) {
        int id = it * 256 + tid;
        int s = id >> 11, rem = id & 2047, n = rem >> 5, col = rem & 31;
        uint32_t dst = sb + 4096 + s * 32768 + n * 512 + ((col ^ (n & 7)) << 4);
        CP_ASYNC16(dst, bsrc[s] + (size_t)n * 512 + col * 16);
    }
    CP_COMMIT();

#pragma unroll 1
    for (int nc = 0; nc < 16; nc++) {
        if (nc < 15) {
            int n0n = (nc + 1) * 64;
            uint32_t bufn = sb + 4096 + ((nc + 1) & 1) * BUF_BYTES;
#pragma unroll
            for (int it = 0; it < 24; it++) {
                int id = it * 256 + tid;
                int s = id >> 11, rem = id & 2047, n = rem >> 5, col = rem & 31;
                uint32_t dst = bufn + s * 32768 + n * 512 + ((col ^ (n & 7)) << 4);
                CP_ASYNC16(dst, bsrc[s] + (size_t)(n0n + n) * 512 + col * 16);
            }
            CP_COMMIT();
            asm volatile("cp.async.wait_group 1;" ::: "memory");
        } else {
            asm volatile("cp.async.wait_group 0;" ::: "memory");
        }
        __syncthreads();

        uint32_t bbase = sb + 4096 + (nc & 1) * BUF_BYTES;
        float acc[4][2][8];
#pragma unroll
        for (int nt = 0; nt < 4; nt++)
#pragma unroll
            for (int mt = 0; mt < 2; mt++)
#pragma unroll
                for (int j = 0; j < 8; j++) acc[nt][mt][j] = 0.f;

#pragma unroll 2
        for (int ks = 0; ks < 16; ks++) {
            uint4 a[3][2];
#pragma unroll
            for (int mt = 0; mt < 2; mt++) {
                size_t o = abase[mt] + ks * 128;
                a[0][mt] = *(const uint4*)(g_ax0f + o);
                a[1][mt] = *(const uint4*)(g_ax1f + o);
                a[2][mt] = *(const uint4*)(g_ax2f + o);
            }
#pragma unroll
            for (int nt = 0; nt < 4; nt++) {
                int nl = nt * 16 + bn;
                uint32_t baddr = bbase + nl * 512 + (((ks * 2 + bkh) ^ (nl & 7)) << 4);
                uint32_t b[3][4];
                LDSM_X4(b[0][0], b[0][1], b[0][2], b[0][3], baddr);
                LDSM_X4(b[1][0], b[1][1], b[1][2], b[1][3], baddr + 32768);
                LDSM_X4(b[2][0], b[2][1], b[2][2], b[2][3], baddr + 65536);
                // 6 split-terms (hh, hm, mh, mm, lh, hl) x 2 mtiles x 2 n-halves
#pragma unroll
                for (int mt = 0; mt < 2; mt++) {
                    const uint32_t* a0 = (const uint32_t*)&a[0][mt];
                    const uint32_t* a1 = (const uint32_t*)&a[1][mt];
                    const uint32_t* a2 = (const uint32_t*)&a[2][mt];
                    float* c0 = acc[nt][mt];
                    float* c1 = acc[nt][mt] + 4;
                    mma16816(c0, a0, b[0][0], b[0][1]);
                    mma16816(c1, a0, b[0][2], b[0][3]);
                    mma16816(c0, a0, b[1][0], b[1][1]);
                    mma16816(c1, a0, b[1][2], b[1][3]);
                    mma16816(c0, a1, b[0][0], b[0][1]);
                    mma16816(c1, a1, b[0][2], b[0][3]);
                    mma16816(c0, a1, b[1][0], b[1][1]);
                    mma16816(c1, a1, b[1][2], b[1][3]);
                    mma16816(c0, a2, b[0][0], b[0][1]);
                    mma16816(c1, a2, b[0][2], b[0][3]);
                    mma16816(c0, a0, b[2][0], b[2][1]);
                    mma16816(c1, a0, b[2][2], b[2][3]);
                }
            }
        }
        // ---- fold argmin: dist = ||e||^2 - 2 acc ----
        int n0 = nc * 64;
#pragma unroll
        for (int nt = 0; nt < 4; nt++)
#pragma unroll
            for (int mt = 0; mt < 2; mt++)
#pragma unroll
                for (int nh = 0; nh < 2; nh++) {
                    int cb = n0 + nt * 16 + nh * 8 + tq * 2;
                    float2 en = *(const float2*)&s_enorm[cb];
                    float* c = &acc[nt][mt][nh * 4];
                    float d0 = en.x - 2.f * c[0];
                    float d1 = en.y - 2.f * c[1];
                    float d2 = en.x - 2.f * c[2];
                    float d3 = en.y - 2.f * c[3];
                    int bi = mt * 2;
                    if (d0 < best[bi]) { best[bi] = d0; bestk[bi] = cb; }
                    if (d1 < best[bi]) { best[bi] = d1; bestk[bi] = cb + 1; }
                    if (d2 < best[bi + 1]) { best[bi + 1] = d2; bestk[bi + 1] = cb; }
                    if (d3 < best[bi + 1]) { best[bi + 1] = d3; bestk[bi + 1] = cb + 1; }
                }
        __syncthreads();   // protect buffer before next-iter staging overwrites it
    }

    // quad reduce (lanes in a quad share token rows)
#pragma unroll
    for (int off = 1; off <= 2; off <<= 1)
#pragma unroll
        for (int i = 0; i < 4; i++) {
            float ov = __shfl_xor_sync(0xffffffffu, best[i], off);
            int   ok = __shfl_xor_sync(0xffffffffu, bestk[i], off);
            if (ov < best[i] || (ov == best[i] && ok < bestk[i])) {
                best[i] = ov; bestk[i] = ok;
            }
        }
    if ((lane & 3) == 0) {
#pragma unroll
        for (int mt = 0; mt < 2; mt++)
#pragma unroll
            for (int h = 0; h < 2; h++) {
                int t = t0 + wid * 32 + mt * 16 + h * 8 + group;
                int bk = bestk[mt * 2 + h];
                g_idx[t] = bk;
                out[O_IDX + t] = (float)bk;
                atomicAdd(&g_cs[bk], 1.0f);
            }
    }
}

// ---------------------------------------------------------------------------
// Gather z_q, vq_loss partials, es segment-sum (v4 atomics, transposed smem)
// ---------------------------------------------------------------------------
__global__ __launch_bounds__(256) void gather_kernel(
    const float* __restrict__ z, const float* __restrict__ embed,
    float* __restrict__ out)
{
    __shared__ float s2[DDIM][33];
    __shared__ int   kidx[32];
    __shared__ float red[256];
    int tid = threadIdx.x;
    int t0 = blockIdx.x * 32;
    int bimg = t0 >> 10, hw0 = t0 & 1023;

    if (tid < 32) kidx[tid] = g_idx[t0 + tid];
    __syncthreads();
#pragma unroll
    for (int l = 0; l < 32; l++)
        s2[tid][l] = embed[(size_t)kidx[l] * DDIM + tid];   // coalesced rows
    __syncthreads();

    int ti = tid & 31, dq = (tid >> 5) * 4;
    int myk = kidx[ti];
    float lsum = 0.f;
    float* outz = out + O_ZQ;
#pragma unroll
    for (int m = 0; m < 8; m++) {
        int d = m * 32 + dq;
        float e0 = s2[d][ti], e1 = s2[d + 1][ti], e2 = s2[d + 2][ti], e3 = s2[d + 3][ti];
        size_t zo = ((size_t)bimg * DDIM + d) * HW + hw0 + ti;
        float z0 = z[zo], z1 = z[zo + HW], z2 = z[zo + 2 * HW], z3 = z[zo + 3 * HW];
        outz[zo] = e0; outz[zo + HW] = e1; outz[zo + 2 * HW] = e2; outz[zo + 3 * HW] = e3;
        float f0 = z0 - e0, f1 = z1 - e1, f2 = z2 - e2, f3 = z3 - e3;
        lsum += f0 * f0 + f1 * f1 + f2 * f2 + f3 * f3;
        asm volatile("red.global.add.v4.f32 [%0], {%1, %2, %3, %4};"
                     :: "l"(&g_es[(size_t)myk * DDIM + d]),
                        "f"(z0), "f"(z1), "f"(z2), "f"(z3) : "memory");
    }
    red[tid] = lsum;
    __syncthreads();
    for (int off = 128; off; off >>= 1) {
        if (tid < off) red[tid] += red[tid + off];
        __syncthreads();
    }
    if (tid == 0) g_partial[blockIdx.x] = red[0];
}

__global__ void loss_kernel(float* __restrict__ out) {
    __shared__ float red[256];
    int tid = threadIdx.x;
    float s = 0.f;
    for (int i = tid; i < 1024; i += 256) s += g_partial[i];
    red[tid] = s; __syncthreads();
    for (int off = 128; off; off >>= 1) {
        if (tid < off) red[tid] += red[tid + off];
        __syncthreads();
    }
    if (tid == 0) out[O_LOSS] = red[0] / 8388608.0f;
}

__global__ void ema_a_kernel(const float* __restrict__ cluster_size,
                             float* __restrict__ out) {
    __shared__ float red[1024];
    int k = threadIdx.x;
    float ncs = cluster_size[k] * DECAY_F + ONE_M_DECAY * g_cs[k];
    out[O_CS + k] = ncs;
    red[k] = ncs; __syncthreads();
    for (int off = 512; off; off >>= 1) {
        if (k < off) red[k] += red[k + off];
        __syncthreads();
    }
    if (k == 0) g_n = red[0];
}

__global__ void ema_b_kernel(const float* __restrict__ embed_avg,
                             float* __restrict__ out) {
    int idx = blockIdx.x * 256 + threadIdx.x;
    int k = idx >> 8;
    float nea = embed_avg[idx] * DECAY_F + ONE_M_DECAY * g_es[idx];
    out[O_EAVG + idx] = nea;
    float ncs = out[O_CS + k];
    float n = g_n;
    float csn = (ncs + EPS_F) / (n + KC * EPS_F) * n;
    out[O_EMB + idx] = nea / csn;
}

// ---------------------------------------------------------------------------
extern "C" void kernel_launch(void* const* d_in, const int* in_sizes, int n_in,
                              void* d_out, int out_size)
{
    const float* z            = (const float*)d_in[0];
    const float* embed        = (const float*)d_in[1];
    const float* cluster_size = (const float*)d_in[2];
    const float* embed_avg    = (const float*)d_in[3];
    float* out = (float*)d_out;

    cudaFuncSetAttribute(dist_hmma_kernel,
                         cudaFuncAttributeMaxDynamicSharedMemorySize, SMEM_TOTAL);

    void* p;
    cudaGetSymbolAddress(&p, g_es);
    cudaMemsetAsync(p, 0, KC * DDIM * sizeof(float));        // launch 1
    cudaGetSymbolAddress(&p, g_cs);
    cudaMemsetAsync(p, 0, KC * sizeof(float));               // launch 2

    enorm_kernel<<<128, 256>>>(embed);                       // launch 3
    split_e_kernel<<<KC * DDIM / 256, 256>>>(embed);         // launch 4
    split_x_kernel<<<NTOK / 32, 256>>>(z);                   // launch 5
    dist_hmma_kernel<<<NTOK / 256, 256, SMEM_TOTAL>>>(out);  // launch 6 <- ncu
    gather_kernel<<<NTOK / 32, 256>>>(z, embed, out);
    loss_kernel<<<1, 256>>>(out);
    ema_a_kernel<<<1, 1024>>>(cluster_size, out);
    ema_b_kernel<<<KC * DDIM / 256, 256>>>(embed_avg, out);
}

// round 6
// speedup vs baseline: 2.1061x; 1.0232x over previous
#include <cuda_runtime.h>
#include <cuda_bf16.h>
#include <cstdint>

#define NTOK 32768
#define DDIM 256
#define KC   1024
#define HW   1024
#define DECAY_F 0.99f
#define ONE_M_DECAY 0.01f
#define EPS_F 1e-5f

// output offsets (concatenated float32 outputs in reference return order)
#define O_ZQ   0
#define O_IDX  8388608
#define O_LOSS 8421376
#define O_EMB  8421377
#define O_CS   8683521
#define O_EAVG 8684545

__device__ float g_es[KC * DDIM];
__device__ float g_cs[KC];
__device__ int   g_idx[NTOK];
__device__ float g_enorm[KC];
__device__ float g_partial[1024];
__device__ float g_n;

// A splits in mma-FRAGMENT-MAJOR layout: u32 idx = tblk16*2048 + ks*128 + lane*4 + frag
__device__ __align__(16) uint32_t g_ax0f[NTOK * 128];
__device__ __align__(16) uint32_t g_ax1f[NTOK * 128];
__device__ __align__(16) uint32_t g_ax2f[NTOK * 128];
// B splits row-major (code-major, 512B rows)
__device__ __align__(16) __nv_bfloat16 g_be0[KC * DDIM];
__device__ __align__(16) __nv_bfloat16 g_be1[KC * DDIM];
__device__ __align__(16) __nv_bfloat16 g_be2[KC * DDIM];

__device__ __forceinline__ uint32_t smem_u32(const void* p) {
    uint32_t a;
    asm("{ .reg .u64 t; cvta.to.shared.u64 t, %1; cvt.u32.u64 %0, t; }"
        : "=r"(a) : "l"(p));
    return a;
}

__device__ __forceinline__ void mma16816(float* c, const uint32_t* a,
                                         uint32_t b0, uint32_t b1) {
    asm volatile(
        "mma.sync.aligned.m16n8k16.row.col.f32.bf16.bf16.f32 "
        "{%0,%1,%2,%3}, {%4,%5,%6,%7}, {%8,%9}, {%0,%1,%2,%3};"
        : "+f"(c[0]), "+f"(c[1]), "+f"(c[2]), "+f"(c[3])
        : "r"(a[0]), "r"(a[1]), "r"(a[2]), "r"(a[3]), "r"(b0), "r"(b1));
}

#define LDSM_X4(r0, r1, r2, r3, addr) \
    asm volatile("ldmatrix.sync.aligned.m8n8.x4.shared.b16 {%0,%1,%2,%3}, [%4];" \
        : "=r"(r0), "=r"(r1), "=r"(r2), "=r"(r3) : "r"(addr))

#define CP_ASYNC16(dst, src) \
    asm volatile("cp.async.cg.shared.global [%0], [%1], 16;" \
                 :: "r"(dst), "l"(src) : "memory")
#define CP_COMMIT() asm volatile("cp.async.commit_group;" ::: "memory")

__device__ __forceinline__ void split3(float v, __nv_bfloat16& h,
                                       __nv_bfloat16& m, __nv_bfloat16& l) {
    h = __float2bfloat16_rn(v);
    float r = v - __bfloat162float(h);
    m = __float2bfloat16_rn(r);
    float r2 = r - __bfloat162float(m);
    l = __float2bfloat16_rn(r2);
}

// ---------------------------------------------------------------------------
// Fused e-split + ||e||^2: one block per code row
// ---------------------------------------------------------------------------
__global__ __launch_bounds__(256) void split_e_enorm_kernel(const float* __restrict__ embed) {
    __shared__ float wsum[8];
    int c = blockIdx.x, tid = threadIdx.x;
    int i = c * DDIM + tid;
    float v = embed[i];
    __nv_bfloat16 h, m, l;
    split3(v, h, m, l);
    g_be0[i] = h; g_be1[i] = m; g_be2[i] = l;
    float s = v * v;
#pragma unroll
    for (int off = 16; off; off >>= 1) s += __shfl_xor_sync(0xffffffffu, s, off);
    if ((tid & 31) == 0) wsum[tid >> 5] = s;
    __syncthreads();
    if (tid == 0) {
        float t = 0.f;
#pragma unroll
        for (int w = 0; w < 8; w++) t += wsum[w];
        g_enorm[c] = t;
    }
}

// token-transpose + split + fragment-major pack
__global__ __launch_bounds__(256) void split_x_kernel(const float* __restrict__ z) {
    __shared__ float s[32][257];
    int tid = threadIdx.x;
    int t0 = blockIdx.x * 32;
    int bimg = t0 >> 10, hw0 = t0 & 1023;
    int d0 = tid >> 5, ti = tid & 31;
#pragma unroll
    for (int mrow = 0; mrow < 32; mrow++) {
        int d = mrow * 8 + d0;
        s[ti][d] = z[((size_t)bimg * DDIM + d) * HW + hw0 + ti];
    }
    __syncthreads();
    size_t obase = (size_t)(t0 >> 4) * 2048;
#pragma unroll
    for (int i = 0; i < 16; i++) {
        int j = i * 256 + tid;
        int tbl = j >> 11, r = j & 2047;
        int ks = r >> 7, L = (r >> 2) & 31, f = r & 3;
        int g = L >> 2, q = L & 3, half = f & 1, kh = f >> 1;
        int tl = tbl * 16 + half * 8 + g;
        int d = ks * 16 + kh * 8 + q * 2;
        float v0 = s[tl][d], v1 = s[tl][d + 1];
        __nv_bfloat16 h0, m0, l0, h1, m1, l1;
        split3(v0, h0, m0, l0);
        split3(v1, h1, m1, l1);
        g_ax0f[obase + j] = ((uint32_t)__bfloat16_as_ushort(h1) << 16) | __bfloat16_as_ushort(h0);
        g_ax1f[obase + j] = ((uint32_t)__bfloat16_as_ushort(m1) << 16) | __bfloat16_as_ushort(m0);
        g_ax2f[obase + j] = ((uint32_t)__bfloat16_as_ushort(l1) << 16) | __bfloat16_as_ushort(l0);
    }
}

// ---------------------------------------------------------------------------
// Distance + argmin: warp-MMA bf16x6 emulated fp32.
// Grid 256 x 128 thr, 2 CTAs/SM -> all 148 SMs busy, gaps overlap.
// CTA = 128 tokens (4 warps x m32) x 1024 codes in 32 n-chunks of 32.
// B double-buffered via cp.async (2 x 48KB); A from gmem/L2 with register
// double-buffer (fragment-major LDG.128). smem total 100KB.
// ---------------------------------------------------------------------------
#define BUF_BYTES 49152
#define SMEM_TOTAL (4096 + 2 * BUF_BYTES)

__global__ __launch_bounds__(128, 2) void dist_hmma_kernel(float* __restrict__ out)
{
    extern __shared__ __align__(1024) char smem[];
    float* s_enorm = (float*)smem;
    uint32_t sb = smem_u32(smem);
    int tid = threadIdx.x, wid = tid >> 5, lane = tid & 31;
    int t0 = blockIdx.x * 128;
    int group = lane >> 2, tq = lane & 3;
    int bn = (lane & 7) + ((lane >> 4) << 3);
    int bkh = (lane >> 3) & 1;

#pragma unroll
    for (int i = 0; i < 8; i++) s_enorm[i * 128 + tid] = g_enorm[i * 128 + tid];

    size_t abase[2];
#pragma unroll
    for (int mt = 0; mt < 2; mt++)
        abase[mt] = (size_t)(blockIdx.x * 8 + wid * 2 + mt) * 2048 + lane * 4;

    float best[4];
    int   bestk[4];
#pragma unroll
    for (int i = 0; i < 4; i++) { best[i] = 3.4e38f; bestk[i] = 0; }

    const char* bsrc[3] = {(const char*)g_be0, (const char*)g_be1, (const char*)g_be2};

    // ---- stage chunk 0: 3 splits x 32 codes x 512B ----
#pragma unroll
    for (int it = 0; it < 24; it++) {
        int id = it * 128 + tid;
        int s = id >> 10, rem = id & 1023, n = rem >> 5, col = rem & 31;
        uint32_t dst = sb + 4096 + s * 16384 + n * 512 + ((col ^ (n & 7)) << 4);
        CP_ASYNC16(dst, bsrc[s] + (size_t)n * 512 + col * 16);
    }
    CP_COMMIT();

#pragma unroll 1
    for (int nc = 0; nc < 32; nc++) {
        if (nc < 31) {
            int n0n = (nc + 1) * 32;
            uint32_t bufn = sb + 4096 + ((nc + 1) & 1) * BUF_BYTES;
#pragma unroll
            for (int it = 0; it < 24; it++) {
                int id = it * 128 + tid;
                int s = id >> 10, rem = id & 1023, n = rem >> 5, col = rem & 31;
                uint32_t dst = bufn + s * 16384 + n * 512 + ((col ^ (n & 7)) << 4);
                CP_ASYNC16(dst, bsrc[s] + (size_t)(n0n + n) * 512 + col * 16);
            }
            CP_COMMIT();
            asm volatile("cp.async.wait_group 1;" ::: "memory");
        } else {
            asm volatile("cp.async.wait_group 0;" ::: "memory");
        }
        __syncthreads();

        uint32_t bbase = sb + 4096 + (nc & 1) * BUF_BYTES;
        float acc[2][2][8];
#pragma unroll
        for (int nt = 0; nt < 2; nt++)
#pragma unroll
            for (int mt = 0; mt < 2; mt++)
#pragma unroll
                for (int j = 0; j < 8; j++) acc[nt][mt][j] = 0.f;

        // register double-buffer on A (hide L2 latency under MMA block)
        uint4 acur[3][2], anxt[3][2];
#pragma unroll
        for (int mt = 0; mt < 2; mt++) {
            acur[0][mt] = *(const uint4*)(g_ax0f + abase[mt]);
            acur[1][mt] = *(const uint4*)(g_ax1f + abase[mt]);
            acur[2][mt] = *(const uint4*)(g_ax2f + abase[mt]);
        }

#pragma unroll 1
        for (int ks = 0; ks < 16; ks++) {
            if (ks < 15) {
#pragma unroll
                for (int mt = 0; mt < 2; mt++) {
                    size_t o = abase[mt] + (ks + 1) * 128;
                    anxt[0][mt] = *(const uint4*)(g_ax0f + o);
                    anxt[1][mt] = *(const uint4*)(g_ax1f + o);
                    anxt[2][mt] = *(const uint4*)(g_ax2f + o);
                }
            }
#pragma unroll
            for (int nt = 0; nt < 2; nt++) {
                int nl = nt * 16 + bn;
                uint32_t baddr = bbase + nl * 512 + (((ks * 2 + bkh) ^ (nl & 7)) << 4);
                uint32_t b[3][4];
                LDSM_X4(b[0][0], b[0][1], b[0][2], b[0][3], baddr);
                LDSM_X4(b[1][0], b[1][1], b[1][2], b[1][3], baddr + 16384);
                LDSM_X4(b[2][0], b[2][1], b[2][2], b[2][3], baddr + 32768);
#pragma unroll
                for (int mt = 0; mt < 2; mt++) {
                    const uint32_t* a0 = (const uint32_t*)&acur[0][mt];
                    const uint32_t* a1 = (const uint32_t*)&acur[1][mt];
                    const uint32_t* a2 = (const uint32_t*)&acur[2][mt];
                    float* c0 = acc[nt][mt];
                    float* c1 = acc[nt][mt] + 4;
                    // 6 split-terms: hh, hm, mh, mm, lh, hl
                    mma16816(c0, a0, b[0][0], b[0][1]);
                    mma16816(c1, a0, b[0][2], b[0][3]);
                    mma16816(c0, a0, b[1][0], b[1][1]);
                    mma16816(c1, a0, b[1][2], b[1][3]);
                    mma16816(c0, a1, b[0][0], b[0][1]);
                    mma16816(c1, a1, b[0][2], b[0][3]);
                    mma16816(c0, a1, b[1][0], b[1][1]);
                    mma16816(c1, a1, b[1][2], b[1][3]);
                    mma16816(c0, a2, b[0][0], b[0][1]);
                    mma16816(c1, a2, b[0][2], b[0][3]);
                    mma16816(c0, a0, b[2][0], b[2][1]);
                    mma16816(c1, a0, b[2][2], b[2][3]);
                }
            }
#pragma unroll
            for (int s = 0; s < 3; s++)
#pragma unroll
                for (int mt = 0; mt < 2; mt++) acur[s][mt] = anxt[s][mt];
        }
        // ---- fold argmin: dist = ||e||^2 - 2 acc ----
        int n0 = nc * 32;
#pragma unroll
        for (int nt = 0; nt < 2; nt++)
#pragma unroll
            for (int mt = 0; mt < 2; mt++)
#pragma unroll
                for (int nh = 0; nh < 2; nh++) {
                    int cb = n0 + nt * 16 + nh * 8 + tq * 2;
                    float2 en = *(const float2*)&s_enorm[cb];
                    float* c = &acc[nt][mt][nh * 4];
                    float d0 = en.x - 2.f * c[0];
                    float d1 = en.y - 2.f * c[1];
                    float d2 = en.x - 2.f * c[2];
                    float d3 = en.y - 2.f * c[3];
                    int bi = mt * 2;
                    if (d0 < best[bi]) { best[bi] = d0; bestk[bi] = cb; }
                    if (d1 < best[bi]) { best[bi] = d1; bestk[bi] = cb + 1; }
                    if (d2 < best[bi + 1]) { best[bi + 1] = d2; bestk[bi + 1] = cb; }
                    if (d3 < best[bi + 1]) { best[bi + 1] = d3; bestk[bi + 1] = cb + 1; }
                }
        __syncthreads();   // protect buffer before next staging overwrites
    }

    // quad reduce (lanes in a quad share token rows)
#pragma unroll
    for (int off = 1; off <= 2; off <<= 1)
#pragma unroll
        for (int i = 0; i < 4; i++) {
            float ov = __shfl_xor_sync(0xffffffffu, best[i], off);
            int   ok = __shfl_xor_sync(0xffffffffu, bestk[i], off);
            if (ov < best[i] || (ov == best[i] && ok < bestk[i])) {
                best[i] = ov; bestk[i] = ok;
            }
        }
    if ((lane & 3) == 0) {
#pragma unroll
        for (int mt = 0; mt < 2; mt++)
#pragma unroll
            for (int h = 0; h < 2; h++) {
                int t = t0 + wid * 32 + mt * 16 + h * 8 + group;
                int bk = bestk[mt * 2 + h];
                g_idx[t] = bk;
                out[O_IDX + t] = (float)bk;
                atomicAdd(&g_cs[bk], 1.0f);
            }
    }
}

// ---------------------------------------------------------------------------
// Gather z_q, vq_loss partials, es segment-sum (v4 atomics, transposed smem)
// ---------------------------------------------------------------------------
__global__ __launch_bounds__(256) void gather_kernel(
    const float* __restrict__ z, const float* __restrict__ embed,
    float* __restrict__ out)
{
    __shared__ float s2[DDIM][33];
    __shared__ int   kidx[32];
    __shared__ float red[256];
    int tid = threadIdx.x;
    int t0 = blockIdx.x * 32;
    int bimg = t0 >> 10, hw0 = t0 & 1023;

    if (tid < 32) kidx[tid] = g_idx[t0 + tid];
    __syncthreads();
#pragma unroll
    for (int l = 0; l < 32; l++)
        s2[tid][l] = embed[(size_t)kidx[l] * DDIM + tid];   // coalesced rows
    __syncthreads();

    int ti = tid & 31, dq = (tid >> 5) * 4;
    int myk = kidx[ti];
    float lsum = 0.f;
    float* outz = out + O_ZQ;
#pragma unroll
    for (int m = 0; m < 8; m++) {
        int d = m * 32 + dq;
        float e0 = s2[d][ti], e1 = s2[d + 1][ti], e2 = s2[d + 2][ti], e3 = s2[d + 3][ti];
        size_t zo = ((size_t)bimg * DDIM + d) * HW + hw0 + ti;
        float z0 = z[zo], z1 = z[zo + HW], z2 = z[zo + 2 * HW], z3 = z[zo + 3 * HW];
        outz[zo] = e0; outz[zo + HW] = e1; outz[zo + 2 * HW] = e2; outz[zo + 3 * HW] = e3;
        float f0 = z0 - e0, f1 = z1 - e1, f2 = z2 - e2, f3 = z3 - e3;
        lsum += f0 * f0 + f1 * f1 + f2 * f2 + f3 * f3;
        asm volatile("red.global.add.v4.f32 [%0], {%1, %2, %3, %4};"
                     :: "l"(&g_es[(size_t)myk * DDIM + d]),
                        "f"(z0), "f"(z1), "f"(z2), "f"(z3) : "memory");
    }
    red[tid] = lsum;
    __syncthreads();
    for (int off = 128; off; off >>= 1) {
        if (tid < off) red[tid] += red[tid + off];
        __syncthreads();
    }
    if (tid == 0) g_partial[blockIdx.x] = red[0];
}

__global__ void loss_kernel(float* __restrict__ out) {
    __shared__ float red[256];
    int tid = threadIdx.x;
    float s = 0.f;
    for (int i = tid; i < 1024; i += 256) s += g_partial[i];
    red[tid] = s; __syncthreads();
    for (int off = 128; off; off >>= 1) {
        if (tid < off) red[tid] += red[tid + off];
        __syncthreads();
    }
    if (tid == 0) out[O_LOSS] = red[0] / 8388608.0f;
}

__global__ void ema_a_kernel(const float* __restrict__ cluster_size,
                             float* __restrict__ out) {
    __shared__ float red[1024];
    int k = threadIdx.x;
    float ncs = cluster_size[k] * DECAY_F + ONE_M_DECAY * g_cs[k];
    out[O_CS + k] = ncs;
    red[k] = ncs; __syncthreads();
    for (int off = 512; off; off >>= 1) {
        if (k < off) red[k] += red[k + off];
        __syncthreads();
    }
    if (k == 0) g_n = red[0];
}

__global__ void ema_b_kernel(const float* __restrict__ embed_avg,
                             float* __restrict__ out) {
    int idx = blockIdx.x * 256 + threadIdx.x;
    int k = idx >> 8;
    float nea = embed_avg[idx] * DECAY_F + ONE_M_DECAY * g_es[idx];
    out[O_EAVG + idx] = nea;
    float ncs = out[O_CS + k];
    float n = g_n;
    float csn = (ncs + EPS_F) / (n + KC * EPS_F) * n;
    out[O_EMB + idx] = nea / csn;
}

// ---------------------------------------------------------------------------
extern "C" void kernel_launch(void* const* d_in, const int* in_sizes, int n_in,
                              void* d_out, int out_size)
{
    const float* z            = (const float*)d_in[0];
    const float* embed        = (const float*)d_in[1];
    const float* cluster_size = (const float*)d_in[2];
    const float* embed_avg    = (const float*)d_in[3];
    float* out = (float*)d_out;

    cudaFuncSetAttribute(dist_hmma_kernel,
                         cudaFuncAttributeMaxDynamicSharedMemorySize, SMEM_TOTAL);

    void* p;
    cudaGetSymbolAddress(&p, g_es);
    cudaMemsetAsync(p, 0, KC * DDIM * sizeof(float));        // launch 1
    cudaGetSymbolAddress(&p, g_cs);
    cudaMemsetAsync(p, 0, KC * sizeof(float));               // launch 2

    split_e_enorm_kernel<<<KC, 256>>>(embed);                // launch 3
    split_x_kernel<<<NTOK / 32, 256>>>(z);                   // launch 4
    dist_hmma_kernel<<<NTOK / 128, 128, SMEM_TOTAL>>>(out);  // launch 5
    gather_kernel<<<NTOK / 32, 256>>>(z, embed, out);        // launch 6 <- ncu
    loss_kernel<<<1, 256>>>(out);
    ema_a_kernel<<<1, 1024>>>(cluster_size, out);
    ema_b_kernel<<<KC * DDIM / 256, 256>>>(embed_avg, out);
}